// round 5
// baseline (speedup 1.0000x reference)
#include <cuda_runtime.h>
#include <cuda_bf16.h>
#include <math.h>

#define B_  16
#define C_  256
#define H_  128
#define W_  128
#define K_  12
#define HW_ (H_ * W_)

#define BAND 4                  // output rows per block / warp
#define NWARP 16                // warps per block
#define NCH  (C_ / NWARP)       // 16 channels per warp
#define BPX  (BAND * W_)        // 512 pixels per band

// ---------------- device scratch ----------------------------------------------
__device__ float g_y[B_ * C_];
__device__ float g_gate[B_ * C_];
__device__ float g_aggw[B_ * C_ * 9];
__device__ float g_mu[B_ * HW_];
__device__ float g_rstd[B_ * HW_];

__device__ __forceinline__ float gelu_exact(float v) {
    return 0.5f * v * (1.0f + erff(v * 0.70710678118654752f));
}
__device__ __forceinline__ float sigmoidf_(float v) {
    return 1.0f / (1.0f + __expf(-v));
}

// ---------------- K1: global average pool per (b,c) ---------------------------
__global__ void gap_kernel(const float* __restrict__ x) {
    __shared__ float red[8];
    const int bc = blockIdx.x;
    const float4* xp = reinterpret_cast<const float4*>(x + (size_t)bc * HW_);
    float s = 0.f;
#pragma unroll
    for (int i = 0; i < 16; i++) {
        float4 v = xp[threadIdx.x + 256 * i];
        s += (v.x + v.y) + (v.z + v.w);
    }
#pragma unroll
    for (int o = 16; o; o >>= 1) s += __shfl_xor_sync(0xffffffffu, s, o);
    if ((threadIdx.x & 31) == 0) red[threadIdx.x >> 5] = s;
    __syncthreads();
    if (threadIdx.x < 8) {
        s = red[threadIdx.x];
#pragma unroll
        for (int o = 4; o; o >>= 1) s += __shfl_xor_sync(0x000000ffu, s, o);
        if (threadIdx.x == 0) g_y[bc] = s * (1.0f / (float)HW_);
    }
}

// ---------------- K2: ECA gate + MLP + softmax + kernel aggregation -----------
__global__ void attn_kernel(const float* __restrict__ w1, const float* __restrict__ b1,
                            const float* __restrict__ w2, const float* __restrict__ b2,
                            const float* __restrict__ kw, const float* __restrict__ eca) {
    const int b = blockIdx.x;
    const int t = threadIdx.x;
    __shared__ float ysm[C_ + 2];
    __shared__ float psm[C_];
    __shared__ float hsm[C_];
    __shared__ float lsm[K_];
    __shared__ float alph[K_];

    ysm[t + 1] = g_y[b * C_ + t];
    if (t == 0) { ysm[0] = 0.f; ysm[C_ + 1] = 0.f; }
    __syncthreads();

    const float e0 = eca[0], e1 = eca[1], e2 = eca[2];
    float gate = sigmoidf_(e0 * ysm[t] + e1 * ysm[t + 1] + e2 * ysm[t + 2]);
    g_gate[b * C_ + t] = gate;
    psm[t] = gate * ysm[t + 1];
    __syncthreads();

    float acc = b1[t];
    for (int c = 0; c < C_; c++) acc += psm[c] * w1[c * C_ + t];
    hsm[t] = gelu_exact(acc);
    __syncthreads();

    if (t < K_) {
        float l = b2[t];
        for (int c = 0; c < C_; c++) l += hsm[c] * w2[c * K_ + t];
        lsm[t] = l;
    }
    __syncthreads();

    if (t == 0) {
        float m = lsm[0];
#pragma unroll
        for (int k = 1; k < K_; k++) m = fmaxf(m, lsm[k]);
        float s = 0.f;
#pragma unroll
        for (int k = 0; k < K_; k++) { float e = __expf(lsm[k] - m); alph[k] = e; s += e; }
        float inv = 1.0f / s;
#pragma unroll
        for (int k = 0; k < K_; k++) alph[k] *= inv;
    }
    __syncthreads();

    for (int idx = t; idx < C_ * 9; idx += 256) {
        float v = 0.f;
#pragma unroll
        for (int k = 0; k < K_; k++) v += alph[k] * kw[k * (C_ * 9) + idx];
        g_aggw[b * (C_ * 9) + idx] = v;
    }
}

// ---------------- register sliding-window conv helpers -------------------------
struct Win { float4 r[6]; };

__device__ __forceinline__ void load_win(const float4* __restrict__ xc4,
                                         int h0, int lane, Win& w) {
#pragma unroll
    for (int r = 0; r < 6; r++) {
        const int gh = h0 - 1 + r;
        if (gh >= 0 && gh < H_) w.r[r] = xc4[gh * (W_ / 4) + lane];
        else                    w.r[r] = make_float4(0.f, 0.f, 0.f, 0.f);
    }
}

__device__ __forceinline__ void shifts(const Win& win, float* L, float* Rv, int lane) {
#pragma unroll
    for (int r = 0; r < 6; r++) {
        float l = __shfl_up_sync(0xffffffffu, win.r[r].w, 1);
        float rr = __shfl_down_sync(0xffffffffu, win.r[r].x, 1);
        L[r]  = (lane == 0)  ? 0.f : l;
        Rv[r] = (lane == 31) ? 0.f : rr;
    }
}

__device__ __forceinline__ float4 conv_row(const Win& win, const float* L, const float* Rv,
                                           const float* w, int j) {
    float4 a;
    const float4 v0 = win.r[j], v1 = win.r[j + 1], v2 = win.r[j + 2];
    a.x  = w[0]*L[j]   + w[1]*v0.x + w[2]*v0.y;
    a.y  = w[0]*v0.x   + w[1]*v0.y + w[2]*v0.z;
    a.z  = w[0]*v0.y   + w[1]*v0.z + w[2]*v0.w;
    a.w  = w[0]*v0.z   + w[1]*v0.w + w[2]*Rv[j];
    a.x += w[3]*L[j+1] + w[4]*v1.x + w[5]*v1.y;
    a.y += w[3]*v1.x   + w[4]*v1.y + w[5]*v1.z;
    a.z += w[3]*v1.y   + w[4]*v1.z + w[5]*v1.w;
    a.w += w[3]*v1.z   + w[4]*v1.w + w[5]*Rv[j+1];
    a.x += w[6]*L[j+2] + w[7]*v2.x + w[8]*v2.y;
    a.y += w[6]*v2.x   + w[7]*v2.y + w[8]*v2.z;
    a.z += w[6]*v2.y   + w[7]*v2.z + w[8]*v2.w;
    a.w += w[6]*v2.z   + w[7]*v2.w + w[8]*Rv[j+2];
    return a;
}

// ---------------- K3a: conv + per-pixel LayerNorm statistics -------------------
// block = (band of 4 rows, b). 16 warps x 16 channels, register sliding window.
// dynamic smem: s_w[C*9] | s_sum[NWARP*BPX] | s_sq[NWARP*BPX]  = 74.75 KB
#define STATS_SMEM_FLOATS (C_ * 9 + 2 * NWARP * BPX)
#define STATS_SMEM_BYTES  (STATS_SMEM_FLOATS * 4)

__global__ void __launch_bounds__(512, 1)
stats_kernel(const float* __restrict__ x) {
    extern __shared__ float smem[];
    float* s_w   = smem;                    // [C*9]
    float* s_sum = s_w + C_ * 9;            // [NWARP*BPX]
    float* s_sq  = s_sum + NWARP * BPX;     // [NWARP*BPX]

    const int tid  = threadIdx.x;
    const int warp = tid >> 5;
    const int lane = tid & 31;
    const int h0   = blockIdx.x * BAND;
    const int b    = blockIdx.y;

    // fold gate into aggregated weights
    for (int i = tid; i < C_ * 9; i += 512)
        s_w[i] = g_aggw[b * (C_ * 9) + i] * g_gate[b * C_ + i / 9];
    __syncthreads();

    const int c0 = warp * NCH;
    const float4* xb = reinterpret_cast<const float4*>(x + ((size_t)b * C_ + c0) * HW_);

    float4 psum[BAND], psq[BAND];
#pragma unroll
    for (int j = 0; j < BAND; j++) {
        psum[j] = make_float4(0.f, 0.f, 0.f, 0.f);
        psq[j]  = make_float4(0.f, 0.f, 0.f, 0.f);
    }

    Win wa, wb;
    load_win(xb, h0, lane, wa);
#pragma unroll
    for (int ci = 0; ci < NCH; ci++) {
        Win& cur = (ci & 1) ? wb : wa;
        Win& nxt = (ci & 1) ? wa : wb;
        if (ci + 1 < NCH)
            load_win(xb + (size_t)(ci + 1) * (HW_ / 4), h0, lane, nxt);
        float L[6], Rv[6];
        shifts(cur, L, Rv, lane);
        const float* wc = s_w + (c0 + ci) * 9;
        float w[9];
#pragma unroll
        for (int i = 0; i < 9; i++) w[i] = wc[i];
#pragma unroll
        for (int j = 0; j < BAND; j++) {
            float4 a = conv_row(cur, L, Rv, w, j);
            psum[j].x += a.x; psum[j].y += a.y; psum[j].z += a.z; psum[j].w += a.w;
            psq[j].x += a.x*a.x; psq[j].y += a.y*a.y; psq[j].z += a.z*a.z; psq[j].w += a.w*a.w;
        }
    }

    // cross-warp reduction over channels
#pragma unroll
    for (int j = 0; j < BAND; j++) {
        const int px = j * W_ + lane * 4;
        *reinterpret_cast<float4*>(&s_sum[warp * BPX + px]) = psum[j];
        *reinterpret_cast<float4*>(&s_sq[warp * BPX + px])  = psq[j];
    }
    __syncthreads();
    {
        const int t = tid;   // 512 threads == 512 band pixels
        float s = 0.f, q = 0.f;
#pragma unroll
        for (int w = 0; w < NWARP; w++) {
            s += s_sum[w * BPX + t];
            q += s_sq[w * BPX + t];
        }
        const float mu  = s * (1.0f / (float)C_);
        const float var = q * (1.0f / (float)C_) - mu * mu;
        g_mu[(size_t)b * HW_ + h0 * W_ + t]   = mu;
        g_rstd[(size_t)b * HW_ + h0 * W_ + t] = rsqrtf(var + 1e-6f);
    }
}

// ---------------- K3b: conv recompute + LN + GELU + residual -------------------
__global__ void __launch_bounds__(512, 1)
apply_kernel(const float* __restrict__ x, const float* __restrict__ gamma,
             const float* __restrict__ beta, float* __restrict__ out) {
    __shared__ float s_w[C_ * 9];
    __shared__ float s_gamma[C_];
    __shared__ float s_beta[C_];

    const int tid  = threadIdx.x;
    const int warp = tid >> 5;
    const int lane = tid & 31;
    const int h0   = blockIdx.x * BAND;
    const int b    = blockIdx.y;

    for (int i = tid; i < C_ * 9; i += 512)
        s_w[i] = g_aggw[b * (C_ * 9) + i] * g_gate[b * C_ + i / 9];
    if (tid < C_) { s_gamma[tid] = gamma[tid]; s_beta[tid] = beta[tid]; }
    __syncthreads();

    // per-pixel LN stats for this warp's 4x128 band (shared by all warps, L1 hits)
    float4 mu4[BAND], rs4[BAND];
#pragma unroll
    for (int j = 0; j < BAND; j++) {
        const size_t o = (size_t)b * HW_ + (size_t)(h0 + j) * W_ + lane * 4;
        mu4[j] = *reinterpret_cast<const float4*>(&g_mu[o]);
        rs4[j] = *reinterpret_cast<const float4*>(&g_rstd[o]);
    }

    const int c0 = warp * NCH;
    const float4* xb = reinterpret_cast<const float4*>(x + ((size_t)b * C_ + c0) * HW_);
    float4* ob = reinterpret_cast<float4*>(out + ((size_t)b * C_ + c0) * HW_);

    Win wa, wb;
    load_win(xb, h0, lane, wa);
#pragma unroll
    for (int ci = 0; ci < NCH; ci++) {
        Win& cur = (ci & 1) ? wb : wa;
        Win& nxt = (ci & 1) ? wa : wb;
        if (ci + 1 < NCH)
            load_win(xb + (size_t)(ci + 1) * (HW_ / 4), h0, lane, nxt);
        float L[6], Rv[6];
        shifts(cur, L, Rv, lane);
        const int c = c0 + ci;
        const float* wc = s_w + c * 9;
        float w[9];
#pragma unroll
        for (int i = 0; i < 9; i++) w[i] = wc[i];
        const float gm = s_gamma[c];
        const float bt = s_beta[c];
#pragma unroll
        for (int j = 0; j < BAND; j++) {
            float4 a = conv_row(cur, L, Rv, w, j);
            const float4 res = cur.r[j + 1];   // center row == residual x
            float4 o;
            o.x = gelu_exact((a.x - mu4[j].x) * rs4[j].x * gm + bt) + res.x;
            o.y = gelu_exact((a.y - mu4[j].y) * rs4[j].y * gm + bt) + res.y;
            o.z = gelu_exact((a.z - mu4[j].z) * rs4[j].z * gm + bt) + res.z;
            o.w = gelu_exact((a.w - mu4[j].w) * rs4[j].w * gm + bt) + res.w;
            ob[(size_t)ci * (HW_ / 4) + (size_t)(h0 + j) * (W_ / 4) + lane] = o;
        }
    }
}

// ---------------- launcher -----------------------------------------------------
extern "C" void kernel_launch(void* const* d_in, const int* in_sizes, int n_in,
                              void* d_out, int out_size) {
    const float* x     = (const float*)d_in[0];
    const float* w1    = (const float*)d_in[1];
    const float* b1    = (const float*)d_in[2];
    const float* w2    = (const float*)d_in[3];
    const float* b2    = (const float*)d_in[4];
    const float* kw    = (const float*)d_in[5];
    const float* eca   = (const float*)d_in[6];
    const float* gamma = (const float*)d_in[7];
    const float* beta  = (const float*)d_in[8];
    float* out = (float*)d_out;

    cudaFuncSetAttribute(stats_kernel, cudaFuncAttributeMaxDynamicSharedMemorySize,
                         STATS_SMEM_BYTES);

    gap_kernel<<<B_ * C_, 256>>>(x);
    attn_kernel<<<B_, 256>>>(w1, b1, w2, b2, kw, eca);
    dim3 grid(H_ / BAND, B_);
    stats_kernel<<<grid, 512, STATS_SMEM_BYTES>>>(x);
    apply_kernel<<<grid, 512>>>(x, gamma, beta, out);
}

// round 6
// speedup vs baseline: 1.6144x; 1.6144x over previous
#include <cuda_runtime.h>
#include <cuda_bf16.h>
#include <math.h>

#define B_  16
#define C_  256
#define H_  128
#define W_  128
#define K_  12
#define HW_ (H_ * W_)

#define BAND 4                   // rows per band
#define NBAND (H_ / BAND)        // 32
#define BPX  (BAND * W_)         // 512 pixels per band
#define SWARP 8                  // warps per stats block
#define SCH  16                  // channels per stats warp (8*16=128 = half of C)
#define ACH  8                   // channels per apply block (1 per warp)

// ---------------- device scratch ----------------------------------------------
__device__ float g_y[B_ * C_];
__device__ float g_gate[B_ * C_];
__device__ float g_aggw[B_ * C_ * 9];
__device__ float g_ps[2][B_ * HW_];   // partial sum   (per channel-half)
__device__ float g_pq[2][B_ * HW_];   // partial sumsq
__device__ float g_mu[B_ * HW_];
__device__ float g_rstd[B_ * HW_];

__device__ __forceinline__ float sigmoidf_(float v) {
    return 1.0f / (1.0f + __expf(-v));
}

// Juffa-style erff: max ~3 ulp; FMA fast path, __expf tail.
__device__ __forceinline__ float fast_erff(float a) {
    float t = fabsf(a);
    float s = a * a;
    float r;
    if (t > 0.921875f) {
        r = fmaf(-1.72853470e-5f, t, 3.83197126e-4f);
        float u = fmaf(-3.88396438e-3f, t, 2.42546219e-2f);
        r = fmaf(r, s, u);
        r = fmaf(r, t, -1.06952421e-1f);
        r = fmaf(r, t, -6.34846687e-1f);
        r = fmaf(r, t, -1.28717512e-1f);
        r = fmaf(r, t, -t);
        r = 1.0f - __expf(r);
        r = copysignf(r, a);
    } else {
        r = -5.96761703e-4f;
        r = fmaf(r, s,  4.99119423e-3f);
        r = fmaf(r, s, -2.67681349e-2f);
        r = fmaf(r, s,  1.12819925e-1f);
        r = fmaf(r, s, -3.76125336e-1f);
        r = fmaf(r, s,  1.28379166e-1f);
        r = fmaf(r, a, a);
    }
    return r;
}
__device__ __forceinline__ float gelu_f(float v) {
    return 0.5f * v * (1.0f + fast_erff(v * 0.70710678118654752f));
}

// ---------------- K1: global average pool per (b,c) ---------------------------
__global__ void gap_kernel(const float* __restrict__ x) {
    __shared__ float red[8];
    const int bc = blockIdx.x;
    const float4* xp = reinterpret_cast<const float4*>(x + (size_t)bc * HW_);
    float s = 0.f;
#pragma unroll
    for (int i = 0; i < 16; i++) {
        float4 v = xp[threadIdx.x + 256 * i];
        s += (v.x + v.y) + (v.z + v.w);
    }
#pragma unroll
    for (int o = 16; o; o >>= 1) s += __shfl_xor_sync(0xffffffffu, s, o);
    if ((threadIdx.x & 31) == 0) red[threadIdx.x >> 5] = s;
    __syncthreads();
    if (threadIdx.x < 8) {
        s = red[threadIdx.x];
#pragma unroll
        for (int o = 4; o; o >>= 1) s += __shfl_xor_sync(0x000000ffu, s, o);
        if (threadIdx.x == 0) g_y[bc] = s * (1.0f / (float)HW_);
    }
}

// ---------------- K2: ECA gate + MLP + softmax + kernel aggregation -----------
__global__ void attn_kernel(const float* __restrict__ w1, const float* __restrict__ b1,
                            const float* __restrict__ w2, const float* __restrict__ b2,
                            const float* __restrict__ kw, const float* __restrict__ eca) {
    const int b = blockIdx.x;
    const int t = threadIdx.x;
    __shared__ float ysm[C_ + 2];
    __shared__ float psm[C_];
    __shared__ float hsm[C_];
    __shared__ float lsm[K_];
    __shared__ float alph[K_];

    ysm[t + 1] = g_y[b * C_ + t];
    if (t == 0) { ysm[0] = 0.f; ysm[C_ + 1] = 0.f; }
    __syncthreads();

    const float e0 = eca[0], e1 = eca[1], e2 = eca[2];
    float gate = sigmoidf_(e0 * ysm[t] + e1 * ysm[t + 1] + e2 * ysm[t + 2]);
    g_gate[b * C_ + t] = gate;
    psm[t] = gate * ysm[t + 1];
    __syncthreads();

    float acc = b1[t];
    for (int c = 0; c < C_; c++) acc += psm[c] * w1[c * C_ + t];
    hsm[t] = 0.5f * acc * (1.0f + erff(acc * 0.70710678118654752f));
    __syncthreads();

    if (t < K_) {
        float l = b2[t];
        for (int c = 0; c < C_; c++) l += hsm[c] * w2[c * K_ + t];
        lsm[t] = l;
    }
    __syncthreads();

    if (t == 0) {
        float m = lsm[0];
#pragma unroll
        for (int k = 1; k < K_; k++) m = fmaxf(m, lsm[k]);
        float s = 0.f;
#pragma unroll
        for (int k = 0; k < K_; k++) { float e = __expf(lsm[k] - m); alph[k] = e; s += e; }
        float inv = 1.0f / s;
#pragma unroll
        for (int k = 0; k < K_; k++) alph[k] *= inv;
    }
    __syncthreads();

    for (int idx = t; idx < C_ * 9; idx += 256) {
        float v = 0.f;
#pragma unroll
        for (int k = 0; k < K_; k++) v += alph[k] * kw[k * (C_ * 9) + idx];
        g_aggw[b * (C_ * 9) + idx] = v;
    }
}

// ---------------- register sliding-window conv helpers -------------------------
struct Win { float4 r[6]; };

__device__ __forceinline__ void load_win(const float4* __restrict__ xc4,
                                         int h0, int lane, Win& w) {
#pragma unroll
    for (int r = 0; r < 6; r++) {
        const int gh = h0 - 1 + r;
        if (gh >= 0 && gh < H_) w.r[r] = xc4[gh * (W_ / 4) + lane];
        else                    w.r[r] = make_float4(0.f, 0.f, 0.f, 0.f);
    }
}

__device__ __forceinline__ void shifts(const Win& win, float* L, float* Rv, int lane) {
#pragma unroll
    for (int r = 0; r < 6; r++) {
        float l  = __shfl_up_sync(0xffffffffu, win.r[r].w, 1);
        float rr = __shfl_down_sync(0xffffffffu, win.r[r].x, 1);
        L[r]  = (lane == 0)  ? 0.f : l;
        Rv[r] = (lane == 31) ? 0.f : rr;
    }
}

__device__ __forceinline__ float4 conv_row(const Win& win, const float* L, const float* Rv,
                                           const float* w, int j) {
    float4 a;
    const float4 v0 = win.r[j], v1 = win.r[j + 1], v2 = win.r[j + 2];
    a.x  = w[0]*L[j]   + w[1]*v0.x + w[2]*v0.y;
    a.y  = w[0]*v0.x   + w[1]*v0.y + w[2]*v0.z;
    a.z  = w[0]*v0.y   + w[1]*v0.z + w[2]*v0.w;
    a.w  = w[0]*v0.z   + w[1]*v0.w + w[2]*Rv[j];
    a.x += w[3]*L[j+1] + w[4]*v1.x + w[5]*v1.y;
    a.y += w[3]*v1.x   + w[4]*v1.y + w[5]*v1.z;
    a.z += w[3]*v1.y   + w[4]*v1.z + w[5]*v1.w;
    a.w += w[3]*v1.z   + w[4]*v1.w + w[5]*Rv[j+1];
    a.x += w[6]*L[j+2] + w[7]*v2.x + w[8]*v2.y;
    a.y += w[6]*v2.x   + w[7]*v2.y + w[8]*v2.z;
    a.z += w[6]*v2.y   + w[7]*v2.z + w[8]*v2.w;
    a.w += w[6]*v2.z   + w[7]*v2.w + w[8]*Rv[j+2];
    return a;
}

// ---------------- K3a: partial LN stats over half the channels -----------------
// block = (band, b, half). 256 threads / 8 warps x 16 channels.
__global__ void __launch_bounds__(256, 3)
stats_kernel(const float* __restrict__ x) {
    __shared__ float s_w[128 * 9];
    __shared__ float s_sum[SWARP * BPX];
    __shared__ float s_sq[SWARP * BPX];

    const int tid  = threadIdx.x;
    const int warp = tid >> 5;
    const int lane = tid & 31;
    const int h0   = blockIdx.x * BAND;
    const int b    = blockIdx.y;
    const int cg   = blockIdx.z;           // 0 or 1: channel half

    for (int i = tid; i < 128 * 9; i += 256) {
        const int gi = cg * 128 * 9 + i;
        s_w[i] = g_aggw[b * (C_ * 9) + gi] * g_gate[b * C_ + cg * 128 + i / 9];
    }
    __syncthreads();

    const int c0 = cg * 128 + warp * SCH;
    const float4* xb = reinterpret_cast<const float4*>(x + ((size_t)b * C_ + c0) * HW_);

    float4 psum[BAND], psq[BAND];
#pragma unroll
    for (int j = 0; j < BAND; j++) {
        psum[j] = make_float4(0.f, 0.f, 0.f, 0.f);
        psq[j]  = make_float4(0.f, 0.f, 0.f, 0.f);
    }

    for (int ci = 0; ci < SCH; ci++) {
        Win win;
        load_win(xb + (size_t)ci * (HW_ / 4), h0, lane, win);
        float L[6], Rv[6];
        shifts(win, L, Rv, lane);
        const float* wc = s_w + (warp * SCH + ci) * 9;
        float w[9];
#pragma unroll
        for (int i = 0; i < 9; i++) w[i] = wc[i];
#pragma unroll
        for (int j = 0; j < BAND; j++) {
            float4 a = conv_row(win, L, Rv, w, j);
            psum[j].x += a.x; psum[j].y += a.y; psum[j].z += a.z; psum[j].w += a.w;
            psq[j].x += a.x*a.x; psq[j].y += a.y*a.y; psq[j].z += a.z*a.z; psq[j].w += a.w*a.w;
        }
    }

#pragma unroll
    for (int j = 0; j < BAND; j++) {
        const int px = j * W_ + lane * 4;
        *reinterpret_cast<float4*>(&s_sum[warp * BPX + px]) = psum[j];
        *reinterpret_cast<float4*>(&s_sq[warp * BPX + px])  = psq[j];
    }
    __syncthreads();

    // 256 threads reduce 512 pixels over 8 warps
    for (int px = tid; px < BPX; px += 256) {
        float s = 0.f, q = 0.f;
#pragma unroll
        for (int w = 0; w < SWARP; w++) {
            s += s_sum[w * BPX + px];
            q += s_sq[w * BPX + px];
        }
        const size_t o = (size_t)b * HW_ + h0 * W_ + px;
        g_ps[cg][o] = s;
        g_pq[cg][o] = q;
    }
}

// ---------------- K3a': combine partials -> mu / rstd --------------------------
__global__ void combine_kernel() {
    const int i = blockIdx.x * 256 + threadIdx.x;   // over B*HW
    const float s = g_ps[0][i] + g_ps[1][i];
    const float q = g_pq[0][i] + g_pq[1][i];
    const float mu  = s * (1.0f / (float)C_);
    const float var = q * (1.0f / (float)C_) - mu * mu;
    g_mu[i]   = mu;
    g_rstd[i] = rsqrtf(var + 1e-6f);
}

// ---------------- K3b: conv recompute + LN + GELU + residual -------------------
// block = (band, b, channel-group of 8). 256 threads / 8 warps x 1 channel.
__global__ void __launch_bounds__(256, 3)
apply_kernel(const float* __restrict__ x, const float* __restrict__ gamma,
             const float* __restrict__ beta, float* __restrict__ out) {
    __shared__ float s_w[ACH * 9];
    __shared__ float s_g[ACH];
    __shared__ float s_b[ACH];
    __shared__ float s_mu[BPX];
    __shared__ float s_rs[BPX];

    const int tid  = threadIdx.x;
    const int warp = tid >> 5;
    const int lane = tid & 31;
    const int h0   = blockIdx.x * BAND;
    const int b    = blockIdx.y;
    const int cz   = blockIdx.z * ACH;      // first channel of this block

    if (tid < ACH * 9)
        s_w[tid] = g_aggw[b * (C_ * 9) + cz * 9 + tid] * g_gate[b * C_ + cz + tid / 9];
    if (tid >= 96 && tid < 96 + ACH)  s_g[tid - 96]  = gamma[cz + tid - 96];
    if (tid >= 128 && tid < 128 + ACH) s_b[tid - 128] = beta[cz + tid - 128];
    // stage LN stats for the band (512 px)
    for (int px = tid; px < BPX; px += 256) {
        const size_t o = (size_t)b * HW_ + h0 * W_ + px;
        s_mu[px] = g_mu[o];
        s_rs[px] = g_rstd[o];
    }
    __syncthreads();

    const int c = cz + warp;
    const float4* xb = reinterpret_cast<const float4*>(x + ((size_t)b * C_ + c) * HW_);
    float4* ob = reinterpret_cast<float4*>(out + ((size_t)b * C_ + c) * HW_);

    Win win;
    load_win(xb, h0, lane, win);
    float L[6], Rv[6];
    shifts(win, L, Rv, lane);
    float w[9];
#pragma unroll
    for (int i = 0; i < 9; i++) w[i] = s_w[warp * 9 + i];
    const float gm = s_g[warp];
    const float bt = s_b[warp];

#pragma unroll
    for (int j = 0; j < BAND; j++) {
        float4 a = conv_row(win, L, Rv, w, j);
        const float4 mu4 = *reinterpret_cast<const float4*>(&s_mu[j * W_ + lane * 4]);
        const float4 rs4 = *reinterpret_cast<const float4*>(&s_rs[j * W_ + lane * 4]);
        const float4 res = win.r[j + 1];            // center row == residual x
        float4 o;
        o.x = gelu_f((a.x - mu4.x) * rs4.x * gm + bt) + res.x;
        o.y = gelu_f((a.y - mu4.y) * rs4.y * gm + bt) + res.y;
        o.z = gelu_f((a.z - mu4.z) * rs4.z * gm + bt) + res.z;
        o.w = gelu_f((a.w - mu4.w) * rs4.w * gm + bt) + res.w;
        ob[(size_t)(h0 + j) * (W_ / 4) + lane] = o;
    }
}

// ---------------- launcher -----------------------------------------------------
extern "C" void kernel_launch(void* const* d_in, const int* in_sizes, int n_in,
                              void* d_out, int out_size) {
    const float* x     = (const float*)d_in[0];
    const float* w1    = (const float*)d_in[1];
    const float* b1    = (const float*)d_in[2];
    const float* w2    = (const float*)d_in[3];
    const float* b2    = (const float*)d_in[4];
    const float* kw    = (const float*)d_in[5];
    const float* eca   = (const float*)d_in[6];
    const float* gamma = (const float*)d_in[7];
    const float* beta  = (const float*)d_in[8];
    float* out = (float*)d_out;

    gap_kernel<<<B_ * C_, 256>>>(x);
    attn_kernel<<<B_, 256>>>(w1, b1, w2, b2, kw, eca);
    dim3 sgrid(NBAND, B_, 2);
    stats_kernel<<<sgrid, 256>>>(x);
    combine_kernel<<<B_ * HW_ / 256, 256>>>();
    dim3 agrid(NBAND, B_, C_ / ACH);
    apply_kernel<<<agrid, 256>>>(x, gamma, beta, out);
}